// round 1
// baseline (speedup 1.0000x reference)
#include <cuda_runtime.h>

// OWA pooling: 3x3 window, stride 2, SAME pad (0 top/left, 1 bottom/right),
// sort window descending, dot with per-channel rank weights.
// inputs: (16,224,224,64) f32 NHWC ; kernel: (9,64) f32 ; out: (16,112,112,64) f32

#define B_  16
#define H_  224
#define W_  224
#define C_  64
#define OH_ 112
#define OW_ 112
#define OW_PER_WARP 14   // 112 / 8 warps

// Descending compare-exchange on float2 (two independent channels)
#define CE(i, j)                                          \
    {                                                     \
        float tx = fmaxf(v[i].x, v[j].x);                 \
        float ty = fmaxf(v[i].y, v[j].y);                 \
        v[j].x = fminf(v[i].x, v[j].x);                   \
        v[j].y = fminf(v[i].y, v[j].y);                   \
        v[i].x = tx;                                      \
        v[i].y = ty;                                      \
    }

__global__ __launch_bounds__(256, 1) void owa_pool_kernel(
    const float* __restrict__ in,   // (B,H,W,C)
    const float* __restrict__ kw,   // (9,C)
    float* __restrict__ out)        // (B,OH,OW,C)
{
    const int oh   = blockIdx.x;
    const int b    = blockIdx.y;
    const int warp = threadIdx.x >> 5;
    const int lane = threadIdx.x & 31;
    const int c    = lane * 2;          // this thread's channel pair

    // Per-rank weights for this channel pair (9 float2 = 18 regs, loop-invariant)
    float2 wgt[9];
#pragma unroll
    for (int k = 0; k < 9; k++)
        wgt[k] = *reinterpret_cast<const float2*>(kw + k * C_ + c);

    const int r0 = oh * 2;
    const bool r2ok = (r0 + 2 < H_);    // bottom pad row when oh == 111
    const float* base = in + ((b * H_ + r0) * W_) * C_ + c;

    // Load one input column (3 rows) of this channel pair; zeros for pad.
    auto loadcol = [&](int col, float2* dst) {
        if (col < W_) {
            dst[0] = *reinterpret_cast<const float2*>(base + col * C_);
            dst[1] = *reinterpret_cast<const float2*>(base + (W_ + col) * C_);
            dst[2] = r2ok
                   ? *reinterpret_cast<const float2*>(base + (2 * W_ + col) * C_)
                   : make_float2(0.f, 0.f);
        } else {                        // right pad column (col == 224+)
            dst[0] = make_float2(0.f, 0.f);
            dst[1] = make_float2(0.f, 0.f);
            dst[2] = make_float2(0.f, 0.f);
        }
    };

    const int ow0 = warp * OW_PER_WARP;

    float2 c0[3], c1[3], c2[3];
    loadcol(2 * ow0,     c0);
    loadcol(2 * ow0 + 1, c1);
    loadcol(2 * ow0 + 2, c2);

    float* orow = out + ((b * OH_ + oh) * OW_) * C_ + c;

#pragma unroll 1
    for (int ow = ow0; ow < ow0 + OW_PER_WARP; ++ow) {
        // Gather window into sort array (copies; c2 stays live for rotation)
        float2 v[9];
        v[0] = c0[0]; v[1] = c0[1]; v[2] = c0[2];
        v[3] = c1[0]; v[4] = c1[1]; v[5] = c1[2];
        v[6] = c2[0]; v[7] = c2[1]; v[8] = c2[2];

        // Rotate columns and issue next iteration's loads NOW so the sort
        // below hides their latency.
        c0[0] = c2[0]; c0[1] = c2[1]; c0[2] = c2[2];
        loadcol(2 * ow + 3, c1);
        loadcol(2 * ow + 4, c2);

        // Optimal 9-input sorting network: 25 CEs, depth 7 (descending).
        CE(0,3) CE(1,7) CE(2,5) CE(4,8)
        CE(0,7) CE(2,4) CE(3,8) CE(5,6)
        CE(0,2) CE(1,3) CE(4,5) CE(7,8)
        CE(1,4) CE(3,6) CE(5,7)
        CE(0,1) CE(2,4) CE(3,5) CE(6,8)
        CE(2,3) CE(4,5) CE(6,7)
        CE(1,2) CE(3,4) CE(5,6)

        // Rank-weighted sum (v[0] is the max, matching -sort(-p))
        float accx = v[0].x * wgt[0].x;
        float accy = v[0].y * wgt[0].y;
#pragma unroll
        for (int k = 1; k < 9; k++) {
            accx = fmaf(v[k].x, wgt[k].x, accx);
            accy = fmaf(v[k].y, wgt[k].y, accy);
        }

        *reinterpret_cast<float2*>(orow + ow * C_) = make_float2(accx, accy);
    }
}

extern "C" void kernel_launch(void* const* d_in, const int* in_sizes, int n_in,
                              void* d_out, int out_size)
{
    const float* in = (const float*)d_in[0];   // (16,224,224,64)
    const float* kw = (const float*)d_in[1];   // (9,64)
    float* out = (float*)d_out;                // (16,112,112,64)

    dim3 grid(OH_, B_);
    dim3 block(256);
    owa_pool_kernel<<<grid, block>>>(in, kw, out);
}